// round 15
// baseline (speedup 1.0000x reference)
#include <cuda_runtime.h>
#include <cuda_fp16.h>
#include <cstdint>

// Problem constants
#define B_   4
#define C_   256
#define H_   160
#define W_   160
#define HW_  (H_ * W_)          // 25600
#define N_   512
#define PH_  8
#define PW_  64

// 50 MB scratch: features transposed to (B, H*W, C) in fp16 so channel reads
// coalesce AND the whole table stays resident in the 126 MB L2.
__device__ __half g_featT[(size_t)B_ * HW_ * C_];

// ---------------------------------------------------------------------------
// Kernel 1: (B, C, H*W) fp32 -> (B, H*W, C) fp16 tiled transpose.
// ---------------------------------------------------------------------------
__global__ void __launch_bounds__(256) transpose_kernel(const float* __restrict__ in)
{
    __shared__ float tile[64][33];

    const int b     = blockIdx.z;
    const int cBase = blockIdx.y * 64;
    const int sBase = blockIdx.x * 32;
    const int tx = threadIdx.x;
    const int ty = threadIdx.y;

    const float* src = in + (size_t)b * C_ * HW_;
#pragma unroll
    for (int j = 0; j < 64; j += 8)
        tile[ty + j][tx] = __ldcs(&src[(size_t)(cBase + ty + j) * HW_ + sBase + tx]);

    __syncthreads();

    __half2* dst2 = (__half2*)(g_featT + (size_t)b * HW_ * C_);
#pragma unroll
    for (int m = 0; m < 4; ++m) {
        const int s = ty + 8 * m;
        const float lo = tile[2 * tx][s];
        const float hi = tile[2 * tx + 1][s];
        dst2[((size_t)(sBase + s) * C_ + cBase) / 2 + tx] = __floats2half2_rn(lo, hi);
    }
}

// ---------------------------------------------------------------------------
// Kernel 2: rotated ROI align, channel-split software pipeline.
// 128-thread blocks, 8192: block owns 32 px of one (n, py) row.
// Channel halves A (groups 0..15) and B (16..31), separate 8 KB tiles.
// Pipeline: phase1-A | bar | B-gathers(2 iters) -> phase2-A stores (in the
// LDG shadow) -> B-compute -> B rest | bar | phase2-B.
// ---------------------------------------------------------------------------
__global__ void __launch_bounds__(128, 10) rroi_kernel(const float* __restrict__ rois,
                                                       float* __restrict__ out)
{
    __shared__ uint4 tileA[32 * 16];        // 32 px x 16 groups x 8 fp16 ch = 8 KB
    __shared__ uint4 tileB[32 * 16];        // 8 KB
    __shared__ uint4 s_wh[32];              // 4x half2-broadcast weights per local px
    __shared__ int4  s_off4[32];            // corner base offsets (uint4 units)

    const int bid = blockIdx.x;
    const int n   = bid >> 4;               // 512 rois
    const int py  = (bid >> 1) & 7;         // 8 rows
    const int h   = bid & 1;                // px half: [32h, 32h+32)
    const int t   = threadIdx.x;

    // ---- per-px sample precompute (threads 0..31) ----
    if (t < 32) {
        const int px = h * 32 + t;

        const float* r = rois + n * 6;
        const int   b  = (int)r[0];
        const float cx = r[1];
        const float cy = r[2];
        const float rh = r[3];
        const float rw = r[4];
        const float th = r[5];

        const float sx = rw * (1.0f / PW_);
        const float sy = rh * (1.0f / PH_);
        const float ct = cosf(th);
        const float st = sinf(th);

        const float yy = ((float)py + 0.5f - PH_ * 0.5f) * sy;
        const float xx = ((float)px + 0.5f - PW_ * 0.5f) * sx;

        const float x = ct * xx + st * yy + cx;
        const float y = -st * xx + ct * yy + cy;

        const float x0f = floorf(x);
        const float y0f = floorf(y);
        const float lx = x - x0f;
        const float ly = y - y0f;
        const int x0 = (int)x0f;
        const int y0 = (int)y0f;
        const int x1 = x0 + 1;
        const int y1 = y0 + 1;

        const bool vx0 = (x0 >= 0) && (x0 < W_);
        const bool vx1 = (x1 >= 0) && (x1 < W_);
        const bool vy0 = (y0 >= 0) && (y0 < H_);
        const bool vy1 = (y1 >= 0) && (y1 < H_);

        const float w00 = (1.0f - lx) * (1.0f - ly) * ((vy0 && vx0) ? 1.0f : 0.0f);
        const float w01 = lx          * (1.0f - ly) * ((vy0 && vx1) ? 1.0f : 0.0f);
        const float w10 = (1.0f - lx) * ly          * ((vy1 && vx0) ? 1.0f : 0.0f);
        const float w11 = lx          * ly          * ((vy1 && vx1) ? 1.0f : 0.0f);

        uint4 wh;
        ((__half2*)&wh)[0] = __half2half2(__float2half_rn(w00));
        ((__half2*)&wh)[1] = __half2half2(__float2half_rn(w01));
        ((__half2*)&wh)[2] = __half2half2(__float2half_rn(w10));
        ((__half2*)&wh)[3] = __half2half2(__float2half_rn(w11));

        const int x0c = min(max(x0, 0), W_ - 1);
        const int x1c = min(max(x1, 0), W_ - 1);
        const int y0c = min(max(y0, 0), H_ - 1);
        const int y1c = min(max(y1, 0), H_ - 1);

        const int base = b * HW_;
        int4 ov;   // offsets in uint4 units (8 halfs): pos * C_/8 = pos * 32
        ov.x = (base + y0c * W_ + x0c) * (C_ / 8);
        ov.y = (base + y0c * W_ + x1c) * (C_ / 8);
        ov.z = (base + y1c * W_ + x0c) * (C_ / 8);
        ov.w = (base + y1c * W_ + x1c) * (C_ / 8);

        s_wh[t]   = wh;
        s_off4[t] = ov;
    }
    __syncthreads();

    const int warp = t >> 5;                // 0..3
    const int lane = t & 31;
    const int sel  = lane >> 4;             // 0 -> px0 of pair, 1 -> px1
    const int g    = lane & 15;             // channel group within half
    const uint4* featU = (const uint4*)g_featT;

    const unsigned out_base = (unsigned)n * (C_ * PH_ * PW_) + (unsigned)py * PW_;

    // interpolate one gathered corner set with half2 weights
    auto interp = [&](int px, const uint4& c0, const uint4& c1,
                      const uint4& c2, const uint4& c3) -> uint4 {
        const uint4 wv = s_wh[px];
        const __half2 w0 = ((const __half2*)&wv)[0];
        const __half2 w1 = ((const __half2*)&wv)[1];
        const __half2 w2 = ((const __half2*)&wv)[2];
        const __half2 w3 = ((const __half2*)&wv)[3];
        uint4 packed;
#pragma unroll
        for (int q = 0; q < 4; ++q) {
            __half2 acc = __hmul2(w0, ((const __half2*)&c0)[q]);
            acc = __hfma2(w1, ((const __half2*)&c1)[q], acc);
            acc = __hfma2(w2, ((const __half2*)&c2)[q], acc);
            acc = __hfma2(w3, ((const __half2*)&c3)[q], acc);
            ((__half2*)&packed)[q] = acc;
        }
        return packed;
    };

    // phase 2 for one half-tile: conflict-free quad LDS.128 -> STG.128
    auto store_half = [&](const uint4* tile, int hb) {
        const int q_ = t & 7;               // px quad 0..7
        const int gg = t >> 3;              // group 0..15 (within half)
        const int col = (gg + q_) & 15;
        const uint4 v0 = tile[(4 * q_ + 0) * 16 + col];
        const uint4 v1 = tile[(4 * q_ + 1) * 16 + col];
        const uint4 v2 = tile[(4 * q_ + 2) * 16 + col];
        const uint4 v3 = tile[(4 * q_ + 3) * 16 + col];
        const int gG = hb + gg;             // global channel group
        const unsigned pxg = (unsigned)h * 32 + 4 * q_;
#pragma unroll
        for (int qq = 0; qq < 4; ++qq) {
            const float2 f0 = __half22float2(((const __half2*)&v0)[qq]);
            const float2 f1 = __half22float2(((const __half2*)&v1)[qq]);
            const float2 f2 = __half22float2(((const __half2*)&v2)[qq]);
            const float2 f3 = __half22float2(((const __half2*)&v3)[qq]);
            const float4 sA = make_float4(f0.x, f1.x, f2.x, f3.x);
            const float4 sB = make_float4(f0.y, f1.y, f2.y, f3.y);
            const unsigned c = (unsigned)(gG * 8 + 2 * qq);
            __stcs((float4*)(out + out_base + c       * (PH_ * PW_) + pxg), sA);
            __stcs((float4*)(out + out_base + (c + 1) * (PH_ * PW_) + pxg), sB);
        }
    };

    // ---- phase 1, half A (channel groups 0..15) ----
#pragma unroll
    for (int i = 0; i < 4; ++i) {
        const int p  = warp * 4 + i;
        const int px = 2 * p + sel;
        const int4 o = s_off4[px];
        const uint4 c0 = __ldg(featU + o.x + g);
        const uint4 c1 = __ldg(featU + o.y + g);
        const uint4 c2 = __ldg(featU + o.z + g);
        const uint4 c3 = __ldg(featU + o.w + g);
        tileA[px * 16 + ((g + (p >> 1)) & 15)] = interp(px, c0, c1, c2, c3);
    }
    __syncthreads();

    // ---- pipelined region: issue half-B gathers, store half A in their shadow ----
    {
        const int p0  = warp * 4 + 0;
        const int p1  = warp * 4 + 1;
        const int pxa = 2 * p0 + sel;
        const int pxb = 2 * p1 + sel;
        const int4 oa = s_off4[pxa];
        const int4 ob = s_off4[pxb];
        // 8 independent gathers issued up front (half B = +16 groups)
        const uint4 a0 = __ldg(featU + oa.x + 16 + g);
        const uint4 a1 = __ldg(featU + oa.y + 16 + g);
        const uint4 a2 = __ldg(featU + oa.z + 16 + g);
        const uint4 a3 = __ldg(featU + oa.w + 16 + g);
        const uint4 b0 = __ldg(featU + ob.x + 16 + g);
        const uint4 b1 = __ldg(featU + ob.y + 16 + g);
        const uint4 b2 = __ldg(featU + ob.z + 16 + g);
        const uint4 b3 = __ldg(featU + ob.w + 16 + g);

        // store half A while the B gathers are in flight (in-order issue:
        // these LDS/STG fill the long-scoreboard window)
        store_half(tileA, 0);

        tileB[pxa * 16 + ((g + (p0 >> 1)) & 15)] = interp(pxa, a0, a1, a2, a3);
        tileB[pxb * 16 + ((g + (p1 >> 1)) & 15)] = interp(pxb, b0, b1, b2, b3);
    }
    // remaining half-B iterations
#pragma unroll
    for (int i = 2; i < 4; ++i) {
        const int p  = warp * 4 + i;
        const int px = 2 * p + sel;
        const int4 o = s_off4[px];
        const uint4 c0 = __ldg(featU + o.x + 16 + g);
        const uint4 c1 = __ldg(featU + o.y + 16 + g);
        const uint4 c2 = __ldg(featU + o.z + 16 + g);
        const uint4 c3 = __ldg(featU + o.w + 16 + g);
        tileB[px * 16 + ((g + (p >> 1)) & 15)] = interp(px, c0, c1, c2, c3);
    }
    __syncthreads();

    // ---- phase 2, half B ----
    store_half(tileB, 16);
}

// ---------------------------------------------------------------------------
extern "C" void kernel_launch(void* const* d_in, const int* in_sizes, int n_in,
                              void* d_out, int out_size)
{
    const float* features = (const float*)d_in[0];
    const float* rois     = (const float*)d_in[1];
    float* out            = (float*)d_out;

    dim3 tgrid(HW_ / 32, C_ / 64, B_);
    dim3 tblk(32, 8);
    transpose_kernel<<<tgrid, tblk>>>(features);

    rroi_kernel<<<N_ * PH_ * 2, 128>>>(rois, out);
}